// round 4
// baseline (speedup 1.0000x reference)
#include <cuda_runtime.h>
#include <cuda_fp16.h>

// Fused upsample2x-bilinear -> affine_grid -> grid_sample_bilinear.
// Separable composition: output = 3x3 weighted sum over ORIGINAL image.
// R4: fp16 overlapped chunks (chunk j = cols 2j..2j+3 as 4x half = 8B), so
// the 3 x-taps per row are ONE aligned LDG.64. Halves L1 data traffic vs f32.

#define N_   8
#define C_   32
#define HI   256
#define WI   256
#define HU   512
#define WU   512
#define WC   128   // chunks per row (WI/2)

// 8*32*256*128 * 8B = 67 MB scratch (device global: allocation-free)
__device__ uint2 g_chunks[N_ * C_ * HI * WC];

// ---------------- prepass: build overlapped fp16 chunks ----------------
__global__ void __launch_bounds__(256)
repack_chunks(const float* __restrict__ x) {
    int t = blockIdx.x * blockDim.x + threadIdx.x;   // one chunk per thread
    int j   = t & (WC - 1);
    int row = t >> 7;                                // (n*C + c)*HI + h
    const float* p = x + (long long)row * WI;
    int c0 = 2 * j;
    float v0 = p[c0];
    float v1 = p[c0 + 1];
    float v2 = p[min(c0 + 2, WI - 1)];
    float v3 = p[min(c0 + 3, WI - 1)];
    __half2 h01 = __floats2half2_rn(v0, v1);
    __half2 h23 = __floats2half2_rn(v2, v3);
    uint2 u;
    u.x = *(const unsigned int*)&h01;
    u.y = *(const unsigned int*)&h23;
    g_chunks[t] = u;
}

// ---------------- main fused kernel ----------------
__device__ __forceinline__ void axis_taps(float f, int U, int O,
                                          int& base, float w[3]) {
    float f0 = floorf(f);
    int   i0 = (int)f0;
    float wf = f - f0;

    w[0] = 0.f; w[1] = 0.f; w[2] = 0.f;
    base = 0;

    #pragma unroll
    for (int k = 0; k < 2; k++) {
        int   t  = i0 + k;
        float Wk = (k == 0) ? (1.0f - wf) : wf;
        Wk = (t >= 0 && t < U) ? Wk : 0.0f;          // zero-padding validity
        int tc = min(max(t, 0), U - 1);
        float s  = fmaxf((float)tc * 0.5f - 0.25f, 0.0f);  // upsample source
        int   o0 = (int)s;
        float wu = s - (float)o0;
        int   o1 = min(o0 + 1, O - 1);
        if (k == 0) base = o0;                       // taps are monotone
        w[o0 - base] += Wk * (1.0f - wu);
        w[o1 - base] += Wk * wu;
    }
}

__global__ void __launch_bounds__(256)
fused_upsample_affine_sample(const float* __restrict__ theta,
                             float* __restrict__ out) {
    // 16x2 warp tiles: lane = (lx in [0,16), ly in [0,2))
    int wid  = blockIdx.x * 8 + (threadIdx.x >> 5);
    int lane = threadIdx.x & 31;
    int xo = ((wid & 31) << 4) | (lane & 15);          // 32 tiles of 16 in x
    int yo = (((wid >> 5) & 255) << 1) | (lane >> 4);  // 256 tiles of 2 in y
    int n  = wid >> 13;

    // affine grid (reference op order)
    float gxn = (2.0f * (float)xo + 1.0f) / (float)WU - 1.0f;
    float gyn = (2.0f * (float)yo + 1.0f) / (float)HU - 1.0f;
    const float* th = theta + n * 6;
    float gox = __ldg(th + 0) * gxn + __ldg(th + 1) * gyn + __ldg(th + 2);
    float goy = __ldg(th + 3) * gxn + __ldg(th + 4) * gyn + __ldg(th + 5);

    float ix = ((gox + 1.0f) * (float)WU - 1.0f) * 0.5f;
    float iy = ((goy + 1.0f) * (float)HU - 1.0f) * 0.5f;

    float* op = out + (((long long)n * C_) * (long long)(HU * WU))
                    + (long long)yo * WU + xo;

    int ix0 = (int)floorf(ix), iy0 = (int)floorf(iy);
    bool oob = (ix0 < -1) || (ix0 >= WU) || (iy0 < -1) || (iy0 >= HU)
               || !(ix == ix) || !(iy == iy);
    if (oob) {
        #pragma unroll 8
        for (int c = 0; c < C_; c++)
            op[(long long)c * (HU * WU)] = 0.0f;
        return;
    }

    int by, bx;
    float wy[3], wx[3];
    axis_taps(iy, HU, HI, by, wy);
    axis_taps(ix, WU, WI, bx, wx);

    // chunk j holds cols 2j..2j+3; taps bx..bx+2 sit at slots s0..s0+2
    int j  = bx >> 1;
    int s0 = bx & 1;
    float wv0 = (s0 == 0) ? wx[0] : 0.0f;
    float wv1 = (s0 == 0) ? wx[1] : wx[0];
    float wv2 = (s0 == 0) ? wx[2] : wx[1];
    float wv3 = (s0 == 0) ? 0.0f  : wx[2];

    float w00 = wy[0]*wv0, w01 = wy[0]*wv1, w02 = wy[0]*wv2, w03 = wy[0]*wv3;
    float w10 = wy[1]*wv0, w11 = wy[1]*wv1, w12 = wy[1]*wv2, w13 = wy[1]*wv3;
    float w20 = wy[2]*wv0, w21 = wy[2]*wv1, w22 = wy[2]*wv2, w23 = wy[2]*wv3;

    int r0 = min(by,     HI - 1) * WC + j;   // rows beyond edge have wy=0
    int r1 = min(by + 1, HI - 1) * WC + j;
    int r2 = min(by + 2, HI - 1) * WC + j;

    const uint2* xp = g_chunks + (long long)n * C_ * (HI * WC);

    #pragma unroll 4
    for (int c = 0; c < C_; c++) {
        const uint2* p = xp + c * (HI * WC);
        uint2 a = __ldg(p + r0);
        uint2 b = __ldg(p + r1);
        uint2 d = __ldg(p + r2);

        float2 a01 = __half22float2(*(const __half2*)&a.x);
        float2 a23 = __half22float2(*(const __half2*)&a.y);
        float2 b01 = __half22float2(*(const __half2*)&b.x);
        float2 b23 = __half22float2(*(const __half2*)&b.y);
        float2 d01 = __half22float2(*(const __half2*)&d.x);
        float2 d23 = __half22float2(*(const __half2*)&d.y);

        float v = 0.0f;
        v = fmaf(w00, a01.x, v); v = fmaf(w01, a01.y, v);
        v = fmaf(w02, a23.x, v); v = fmaf(w03, a23.y, v);
        v = fmaf(w10, b01.x, v); v = fmaf(w11, b01.y, v);
        v = fmaf(w12, b23.x, v); v = fmaf(w13, b23.y, v);
        v = fmaf(w20, d01.x, v); v = fmaf(w21, d01.y, v);
        v = fmaf(w22, d23.x, v); v = fmaf(w23, d23.y, v);

        op[(long long)c * (HU * WU)] = v;
    }
}

extern "C" void kernel_launch(void* const* d_in, const int* in_sizes, int n_in,
                              void* d_out, int out_size) {
    const float* x     = (const float*)d_in[0];
    const float* theta = (const float*)d_in[1];
    float*       out   = (float*)d_out;

    // prepass: 8.39M chunks, one per thread
    repack_chunks<<<(N_ * C_ * HI * WC) / 256, 256>>>(x);
    // main: 65536 warps (16x2 tile each), 8 warps per block
    fused_upsample_affine_sample<<<8192, 256>>>(theta, out);
}

// round 5
// speedup vs baseline: 1.2432x; 1.2432x over previous
#include <cuda_runtime.h>

// Fused upsample2x-bilinear -> affine_grid -> grid_sample_bilinear.
// Separable composition: output = 3x3 weighted sum over ORIGINAL image.
// R5: f32 overlapped chunks (prepass) + per-image adaptive warp-tile shape
// chosen from theta to minimize distinct-L1-lines per load instruction.

#define N_   8
#define C_   32
#define HI   256
#define WI   256
#define HU   512
#define WU   512
#define WC   128   // chunks per row (WI/2)

// 8*32*256*128 float4 = 134 MB scratch (device global: allocation-free)
__device__ float4 g_chunks[N_ * C_ * HI * WC];

// ---------------- prepass: build overlapped chunks ----------------
__global__ void __launch_bounds__(256)
repack_chunks(const float* __restrict__ x) {
    int t = blockIdx.x * blockDim.x + threadIdx.x;   // one chunk per thread
    int j   = t & (WC - 1);
    int row = t >> 7;                                // (n*C + c)*HI + h
    const float* p = x + (long long)row * WI;
    int c0 = 2 * j;
    float4 v;
    v.x = p[c0];
    v.y = p[c0 + 1];
    v.z = p[min(c0 + 2, WI - 1)];
    v.w = p[min(c0 + 3, WI - 1)];
    g_chunks[t] = v;
}

// ---------------- main fused kernel ----------------
__device__ __forceinline__ void axis_taps(float f, int U, int O,
                                          int& base, float w[3]) {
    float f0 = floorf(f);
    int   i0 = (int)f0;
    float wf = f - f0;

    w[0] = 0.f; w[1] = 0.f; w[2] = 0.f;
    base = 0;

    #pragma unroll
    for (int k = 0; k < 2; k++) {
        int   t  = i0 + k;
        float Wk = (k == 0) ? (1.0f - wf) : wf;
        Wk = (t >= 0 && t < U) ? Wk : 0.0f;          // zero-padding validity
        int tc = min(max(t, 0), U - 1);
        float s  = fmaxf((float)tc * 0.5f - 0.25f, 0.0f);  // upsample source
        int   o0 = (int)s;
        float wu = s - (float)o0;
        int   o1 = min(o0 + 1, O - 1);
        if (k == 0) base = o0;                       // taps are monotone
        w[o0 - base] += Wk * (1.0f - wu);
        w[o1 - base] += Wk * wu;
    }
}

// Estimated L1 wavefronts for a (Tx,Ty) warp tile given |theta| entries.
__device__ __forceinline__ float tile_cost(float a00, float a01,
                                           float a10, float a11,
                                           float Tx, float Ty) {
    float rows = 0.5f * (a10 * (Tx - 1.f) + a11 * (Ty - 1.f)) + 3.0f;
    float colB = 4.0f * (a00 * (Tx - 1.f) + a01 * (Ty - 1.f)) + 16.0f;
    return 3.0f * rows * (colB * 0.0078125f + 1.0f) + Ty;   // loads + stores
}

__global__ void __launch_bounds__(256)
fused_upsample_affine_sample(const float* __restrict__ theta,
                             float* __restrict__ out) {
    int wid  = blockIdx.x * 8 + (threadIdx.x >> 5);
    int lane = threadIdx.x & 31;
    int n = wid >> 13;          // 8192 warps per image
    int r = wid & 8191;

    const float* th = theta + n * 6;
    float t0 = __ldg(th + 0), t1 = __ldg(th + 1), t2 = __ldg(th + 2);
    float t3 = __ldg(th + 3), t4 = __ldg(th + 4), t5 = __ldg(th + 5);

    // Per-image tile shape: s=0 -> 16x2, s=1 -> 8x4, s=2 -> 4x8.
    float a00 = fabsf(t0), a01 = fabsf(t1), a10 = fabsf(t3), a11 = fabsf(t4);
    float c0s = tile_cost(a00, a01, a10, a11, 16.f, 2.f);
    float c1s = tile_cost(a00, a01, a10, a11,  8.f, 4.f);
    float c2s = tile_cost(a00, a01, a10, a11,  4.f, 8.f);
    int s = 0;
    float cb = c0s;
    if (c1s < cb) { s = 1; cb = c1s; }
    if (c2s < cb) { s = 2; }

    // Decode (xo, yo): tilesX = 32<<s, Tx = 16>>s, Ty = 2<<s.
    int tx = r & ((32 << s) - 1);
    int ty = r >> (5 + s);
    int lx = lane & ((16 >> s) - 1);
    int ly = lane >> (4 - s);
    int xo = (tx << (4 - s)) | lx;
    int yo = (ty << (1 + s)) | ly;

    // affine grid (reference op order)
    float gxn = (2.0f * (float)xo + 1.0f) / (float)WU - 1.0f;
    float gyn = (2.0f * (float)yo + 1.0f) / (float)HU - 1.0f;
    float gox = t0 * gxn + t1 * gyn + t2;
    float goy = t3 * gxn + t4 * gyn + t5;

    float ix = ((gox + 1.0f) * (float)WU - 1.0f) * 0.5f;
    float iy = ((goy + 1.0f) * (float)HU - 1.0f) * 0.5f;

    float* op = out + (((long long)n * C_) * (long long)(HU * WU))
                    + (long long)yo * WU + xo;

    int ix0 = (int)floorf(ix), iy0 = (int)floorf(iy);
    bool oob = (ix0 < -1) || (ix0 >= WU) || (iy0 < -1) || (iy0 >= HU)
               || !(ix == ix) || !(iy == iy);
    if (oob) {
        #pragma unroll 8
        for (int c = 0; c < C_; c++)
            op[(long long)c * (HU * WU)] = 0.0f;
        return;
    }

    int by, bx;
    float wy[3], wx[3];
    axis_taps(iy, HU, HI, by, wy);
    axis_taps(ix, WU, WI, bx, wx);

    // chunk j holds cols 2j..2j+3; taps bx..bx+2 sit at slots s0..s0+2
    int j  = bx >> 1;
    int s0 = bx & 1;
    float wv0 = (s0 == 0) ? wx[0] : 0.0f;
    float wv1 = (s0 == 0) ? wx[1] : wx[0];
    float wv2 = (s0 == 0) ? wx[2] : wx[1];
    float wv3 = (s0 == 0) ? 0.0f  : wx[2];

    float w00 = wy[0]*wv0, w01 = wy[0]*wv1, w02 = wy[0]*wv2, w03 = wy[0]*wv3;
    float w10 = wy[1]*wv0, w11 = wy[1]*wv1, w12 = wy[1]*wv2, w13 = wy[1]*wv3;
    float w20 = wy[2]*wv0, w21 = wy[2]*wv1, w22 = wy[2]*wv2, w23 = wy[2]*wv3;

    int r0 = min(by,     HI - 1) * WC + j;   // rows beyond edge have wy=0
    int r1 = min(by + 1, HI - 1) * WC + j;
    int r2 = min(by + 2, HI - 1) * WC + j;

    const float4* xp = g_chunks + (long long)n * C_ * (HI * WC);

    #pragma unroll 4
    for (int c = 0; c < C_; c++) {
        const float4* p = xp + c * (HI * WC);
        float4 a = __ldg(p + r0);
        float4 b = __ldg(p + r1);
        float4 d = __ldg(p + r2);

        float v = 0.0f;
        v = fmaf(w00, a.x, v); v = fmaf(w01, a.y, v);
        v = fmaf(w02, a.z, v); v = fmaf(w03, a.w, v);
        v = fmaf(w10, b.x, v); v = fmaf(w11, b.y, v);
        v = fmaf(w12, b.z, v); v = fmaf(w13, b.w, v);
        v = fmaf(w20, d.x, v); v = fmaf(w21, d.y, v);
        v = fmaf(w22, d.z, v); v = fmaf(w23, d.w, v);

        op[(long long)c * (HU * WU)] = v;
    }
}

extern "C" void kernel_launch(void* const* d_in, const int* in_sizes, int n_in,
                              void* d_out, int out_size) {
    const float* x     = (const float*)d_in[0];
    const float* theta = (const float*)d_in[1];
    float*       out   = (float*)d_out;

    // prepass: 8.39M chunks, one per thread
    repack_chunks<<<(N_ * C_ * HI * WC) / 256, 256>>>(x);
    // main: 65536 warps (adaptive tile each), 8 warps per block
    fused_upsample_affine_sample<<<8192, 256>>>(theta, out);
}